// round 8
// baseline (speedup 1.0000x reference)
#include <cuda_runtime.h>
#include <cuda_bf16.h>
#include <cstdint>
#include <cstddef>

#define T_DIM  32
#define K2     512
#define KD     262144
#define THRESH 0.2f

#define KSPLIT 74
#define KSLAB  32                          // fp32 k per pipeline stage
#define NSLAB_TOT (KD / KSLAB)             // 8192
#define SBASE (NSLAB_TOT / KSPLIT)         // 110
#define SREM  (NSLAB_TOT - SBASE * KSPLIT) // 52

#define STAGES   4
#define A_STRIDE 144                       // 128B data + 16B pad per W row
#define A_BYTES  (128 * A_STRIDE)          // 18432
#define B_OFF    A_BYTES
#define B_STRIDE 160                       // 128B fp32 data + 32B pad (2-way min)
#define STAGE_BYTES (A_BYTES + 32 * B_STRIDE)   // 23552
#define SMEM_TOTAL  (STAGES * STAGE_BYTES)      // 94208

__device__ float g_partial[(size_t)KSPLIT * T_DIM * K2];
__device__ float g_dot[T_DIM * K2];

// ---------------- helpers ----------------
__device__ __forceinline__ uint32_t smem_u32(const void* p) {
    uint32_t a;
    asm("{ .reg .u64 t; cvta.to.shared.u64 t, %1; cvt.u32.u64 %0, t; }"
        : "=r"(a) : "l"(p));
    return a;
}
__device__ __forceinline__ void cp16(uint32_t dst, const void* src) {
    asm volatile("cp.async.cg.shared.global [%0], [%1], 16;"
                 :: "r"(dst), "l"(src) : "memory");
}
__device__ __forceinline__ float2 lds64(uint32_t a) {
    float2 v;
    asm volatile("ld.shared.v2.f32 {%0,%1}, [%2];"
                 : "=f"(v.x), "=f"(v.y) : "r"(a));
    return v;
}
__device__ __forceinline__ void mma_bf16(float* c, const uint32_t* a, const uint32_t* b) {
    asm volatile("mma.sync.aligned.m16n8k16.row.col.f32.bf16.bf16.f32 "
                 "{%0,%1,%2,%3}, {%4,%5,%6,%7}, {%8,%9}, {%0,%1,%2,%3};"
                 : "+f"(c[0]), "+f"(c[1]), "+f"(c[2]), "+f"(c[3])
                 : "r"(a[0]), "r"(a[1]), "r"(a[2]), "r"(a[3]),
                   "r"(b[0]), "r"(b[1]));
}
__device__ __forceinline__ void cvt2(float a, float b, uint32_t& h, uint32_t& l) {
    __nv_bfloat162 hb = __floats2bfloat162_rn(a, b);
    float2 hf = __bfloat1622float2(hb);
    __nv_bfloat162 lb = __floats2bfloat162_rn(a - hf.x, b - hf.y);
    h = *reinterpret_cast<uint32_t*>(&hb);
    l = *reinterpret_cast<uint32_t*>(&lb);
}

// ---------------------------------------------------------------------------
// cp.async-pipelined HMMA GEMM: partial[sp][t][o] = sum_k rec[t][k]*w[o][k]
// A (W) fp32-staged + reg-split; B (rec) fp32-staged + reg-split.
// bf16 3-product (hh+hl+lh), fp32 accum. warp = 16 o x 32 t.
// ---------------------------------------------------------------------------
__global__ void __launch_bounds__(256, 2)
gemm_pipe(const float* __restrict__ rec, const float* __restrict__ wgt)
{
    extern __shared__ __align__(128) char smem[];
    const uint32_t sbase = smem_u32(smem);

    const int tid = threadIdx.x;
    const int wid = tid >> 5;
    const int lid = tid & 31;
    const int g   = lid >> 2;
    const int tig = lid & 3;
    const int ot  = blockIdx.x;        // 0..3
    const int sp  = blockIdx.y;        // 0..73
    const int obase = ot * 128;

    const int s_begin = sp * SBASE + (sp < SREM ? sp : SREM);
    const int s_count = SBASE + (sp < SREM ? 1 : 0);

    // ---- staging maps ----
    const float* asrc[4];
    uint32_t adst[4];
#pragma unroll
    for (int j = 0; j < 4; j++) {
        const int i = tid + 256 * j;
        const int arow = i >> 3, achk = i & 7;
        asrc[j] = wgt + (size_t)(obase + arow) * KD + achk * 4;
        adst[j] = sbase + (uint32_t)(arow * A_STRIDE + achk * 16);
    }
    const int brow = tid >> 3, bchk = tid & 7;
    const float* bsrc = rec + (size_t)brow * KD + bchk * 4;
    const uint32_t bdst = sbase + (uint32_t)(B_OFF + brow * B_STRIDE + bchk * 16);

#define ISSUE(S)                                                              \
    {   const uint32_t so = (uint32_t)((S) & 3) * STAGE_BYTES;                 \
        const size_t ko = (size_t)(s_begin + (S)) * KSLAB;                     \
        _Pragma("unroll") for (int j = 0; j < 4; j++)                          \
            cp16(adst[j] + so, asrc[j] + ko);                                  \
        cp16(bdst + so, bsrc + ko); }

    // ---- compute lane addresses ----
    const uint32_t a0b = sbase + (uint32_t)((wid * 16 + g) * A_STRIDE + tig * 8);
    const uint32_t a1b = a0b + 8 * A_STRIDE;
    const uint32_t bb  = sbase + (uint32_t)(B_OFF + g * B_STRIDE + tig * 8);

    float acc[4][4];
#pragma unroll
    for (int nt = 0; nt < 4; nt++)
#pragma unroll
        for (int i = 0; i < 4; i++) acc[nt][i] = 0.0f;

    ISSUE(0) asm volatile("cp.async.commit_group;" ::: "memory");
    ISSUE(1) asm volatile("cp.async.commit_group;" ::: "memory");
    ISSUE(2) asm volatile("cp.async.commit_group;" ::: "memory");

    for (int s = 0; s < s_count; s++) {
        asm volatile("cp.async.wait_group 2;" ::: "memory");
        __syncthreads();
        if (s + 3 < s_count) ISSUE(s + 3)
        asm volatile("cp.async.commit_group;" ::: "memory");

        const uint32_t so = (uint32_t)(s & 3) * STAGE_BYTES;
#pragma unroll
        for (int ks = 0; ks < 2; ks++) {
            // A fragments: rows {orow, orow+8}, k pairs {2tig, 2tig+8}
            const uint32_t ao = so + ks * 64;
            const float2 f0 = lds64(a0b + ao);
            const float2 f1 = lds64(a1b + ao);
            const float2 f2 = lds64(a0b + ao + 32);
            const float2 f3 = lds64(a1b + ao + 32);
            uint32_t Ah[4], Al[4];
            cvt2(f0.x, f0.y, Ah[0], Al[0]);
            cvt2(f1.x, f1.y, Ah[1], Al[1]);
            cvt2(f2.x, f2.y, Ah[2], Al[2]);
            cvt2(f3.x, f3.y, Ah[3], Al[3]);
            const uint32_t bo = bb + so + ks * 64;
#pragma unroll
            for (int nt = 0; nt < 4; nt++) {
                // B fragment: t = nt*8+g, k pairs {2tig, 2tig+8}
                const float2 b0 = lds64(bo + nt * (8 * B_STRIDE));
                const float2 b1 = lds64(bo + nt * (8 * B_STRIDE) + 32);
                uint32_t Bh[2], Bl[2];
                cvt2(b0.x, b0.y, Bh[0], Bl[0]);
                cvt2(b1.x, b1.y, Bh[1], Bl[1]);
                mma_bf16(acc[nt], Ah, Bh);   // hh
                mma_bf16(acc[nt], Ah, Bl);   // hl
                mma_bf16(acc[nt], Al, Bh);   // lh
            }
        }
    }

    // epilogue
    const int orow = obase + wid * 16 + g;
#pragma unroll
    for (int nt = 0; nt < 4; nt++)
#pragma unroll
        for (int c = 0; c < 4; c++) {
            const int o = orow + ((c >> 1) ? 8 : 0);
            const int t = nt * 8 + 2 * tig + (c & 1);
            g_partial[((size_t)sp * T_DIM + t) * K2 + o] = acc[nt][c];
        }
}

// ---------------------------------------------------------------------------
// deterministic split-K reduction
// ---------------------------------------------------------------------------
__global__ void __launch_bounds__(512) reduce_kernel()
{
    const int t = blockIdx.x;
    const int o = threadIdx.x;
    const size_t stride = (size_t)T_DIM * K2;
    const size_t idx = (size_t)t * K2 + o;
    float s = 0.0f;
#pragma unroll
    for (int sp = 0; sp < KSPLIT; sp++)
        s += g_partial[(size_t)sp * stride + idx];
    g_dot[t * K2 + o] = s;
}

// ---------------------------------------------------------------------------
// post: threshold -> first-spike -> totals -> 8-round k-WTA (shuffle argmax)
// ---------------------------------------------------------------------------
__global__ void __launch_bounds__(512) post_kernel(float* __restrict__ outp)
{
    const int o    = threadIdx.x;
    const int lane = o & 31;
    const int w    = o >> 5;

    unsigned mask = 0;
    int cnt = 0;
#pragma unroll
    for (int t = 0; t < T_DIM; t++) {
        const float v = g_dot[t * K2 + o];
        if (v >= THRESH) { cnt++; mask |= (1u << t); }
    }
    int first = T_DIM - cnt;
    if (first > T_DIM - 1) first = T_DIM - 1;
    const float fv    = g_dot[first * K2 + o];
    const float value = (fv < THRESH) ? 0.0f : fv;
    const float cand  = (cnt > 0) ? value : 0.0f;

    __shared__ float wmaxf[16];
    __shared__ unsigned long long wmax[16];
    __shared__ int s_win;

    // global max of cand (all values >= 0)
    float m = cand;
#pragma unroll
    for (int off = 16; off; off >>= 1)
        m = fmaxf(m, __shfl_xor_sync(0xffffffffu, m, off));
    if (lane == 0) wmaxf[w] = m;
    __syncthreads();
    if (o == 0) {
        float mm = wmaxf[0];
#pragma unroll
        for (int i = 1; i < 16; i++) mm = fmaxf(mm, wmaxf[i]);
        wmaxf[0] = mm;
    }
    __syncthreads();
    const float voff = wmaxf[0] * (float)T_DIM;

    float tot = (cnt > 0) ? (float)cnt * (value + voff) : 0.0f;
    bool sel = false;

    for (int r = 0; r < 8; r++) {
        // packed key: nonneg float bits order-preserving; smaller idx wins ties
        unsigned long long pk =
            ((unsigned long long)__float_as_uint(tot) << 32)
            | (unsigned)(K2 - 1 - o);
#pragma unroll
        for (int off = 16; off; off >>= 1) {
            unsigned long long other = __shfl_xor_sync(0xffffffffu, pk, off);
            if (other > pk) pk = other;
        }
        if (lane == 0) wmax[w] = pk;
        __syncthreads();
        if (o == 0) {
            unsigned long long best = wmax[0];
#pragma unroll
            for (int i = 1; i < 16; i++) if (wmax[i] > best) best = wmax[i];
            s_win = (K2 - 1) - (int)(unsigned)(best & 0xffffffffULL);
        }
        __syncthreads();
        if (o == s_win) {
            if (tot != 0.0f) sel = true;
            tot = 0.0f;
        }
        __syncthreads();
    }

#pragma unroll
    for (int t = 0; t < T_DIM; t++) {
        outp[t * K2 + o] = (sel && ((mask >> t) & 1u)) ? 1.0f : 0.0f;
    }
}

// ---------------------------------------------------------------------------
extern "C" void kernel_launch(void* const* d_in, const int* in_sizes, int n_in,
                              void* d_out, int out_size)
{
    const float* rec = (const float*)d_in[0];   // (32,1,64,4096)
    const float* wgt = (const float*)d_in[1];   // (512,1,64,4096)
    if (n_in >= 2 && in_sizes[0] > in_sizes[1]) {
        const float* tmp = rec; rec = wgt; wgt = tmp;
    }
    float* outp = (float*)d_out;

    cudaFuncSetAttribute(gemm_pipe, cudaFuncAttributeMaxDynamicSharedMemorySize,
                         SMEM_TOTAL);

    gemm_pipe<<<dim3(4, KSPLIT), 256, SMEM_TOTAL>>>(rec, wgt);
    reduce_kernel<<<T_DIM, K2>>>();
    post_kernel<<<1, K2>>>(outp);
}

// round 9
// speedup vs baseline: 1.0144x; 1.0144x over previous
#include <cuda_runtime.h>
#include <cuda_bf16.h>
#include <cstdint>
#include <cstddef>

#define T_DIM  32
#define K2     512
#define KD     262144
#define THRESH 0.2f

#define KSPLIT 74
#define KSLAB  32                          // fp32 k per pipeline stage
#define NSLAB_TOT (KD / KSLAB)             // 8192
#define SBASE (NSLAB_TOT / KSPLIT)         // 110
#define SREM  (NSLAB_TOT - SBASE * KSPLIT) // 52

#define STAGES   3
#define A_STRIDE 144                       // 128B data + 16B pad per W row
#define A_BYTES  (128 * A_STRIDE)          // 18432
#define BF_OFF   A_BYTES                   // B fp32 staging: 32 x 144B
#define BF_STRIDE 144
#define BH_OFF   (BF_OFF + 32 * BF_STRIDE)
#define BB_STRIDE 80                       // bf16 rows: 64B data + 16B pad
#define BL_OFF   (BH_OFF + 32 * BB_STRIDE)
#define STAGE_BYTES (BL_OFF + 32 * BB_STRIDE)   // 28160
#define SMEM_TOTAL  (STAGES * STAGE_BYTES)      // 84480

__device__ float g_partial[(size_t)KSPLIT * T_DIM * K2];
__device__ float g_dot[T_DIM * K2];

// ---------------- helpers ----------------
__device__ __forceinline__ uint32_t smem_u32(const void* p) {
    uint32_t a;
    asm("{ .reg .u64 t; cvta.to.shared.u64 t, %1; cvt.u32.u64 %0, t; }"
        : "=r"(a) : "l"(p));
    return a;
}
__device__ __forceinline__ void cp16(uint32_t dst, const void* src) {
    asm volatile("cp.async.cg.shared.global [%0], [%1], 16;"
                 :: "r"(dst), "l"(src) : "memory");
}
__device__ __forceinline__ float2 lds64(uint32_t a) {
    float2 v;
    asm volatile("ld.shared.v2.f32 {%0,%1}, [%2];"
                 : "=f"(v.x), "=f"(v.y) : "r"(a));
    return v;
}
__device__ __forceinline__ float4 lds128(uint32_t a) {
    float4 v;
    asm volatile("ld.shared.v4.f32 {%0,%1,%2,%3}, [%4];"
                 : "=f"(v.x), "=f"(v.y), "=f"(v.z), "=f"(v.w) : "r"(a));
    return v;
}
__device__ __forceinline__ void sts64(uint32_t a, uint32_t x, uint32_t y) {
    asm volatile("st.shared.v2.b32 [%0], {%1,%2};" :: "r"(a), "r"(x), "r"(y)
                 : "memory");
}
__device__ __forceinline__ void ldsm_x2(uint32_t* r, uint32_t addr) {
    asm volatile("ldmatrix.sync.aligned.m8n8.x2.shared.b16 {%0,%1}, [%2];"
                 : "=r"(r[0]), "=r"(r[1]) : "r"(addr));
}
__device__ __forceinline__ void mma_bf16(float* c, const uint32_t* a, const uint32_t* b) {
    asm volatile("mma.sync.aligned.m16n8k16.row.col.f32.bf16.bf16.f32 "
                 "{%0,%1,%2,%3}, {%4,%5,%6,%7}, {%8,%9}, {%0,%1,%2,%3};"
                 : "+f"(c[0]), "+f"(c[1]), "+f"(c[2]), "+f"(c[3])
                 : "r"(a[0]), "r"(a[1]), "r"(a[2]), "r"(a[3]),
                   "r"(b[0]), "r"(b[1]));
}
__device__ __forceinline__ void cvt2(float a, float b, uint32_t& h, uint32_t& l) {
    __nv_bfloat162 hb = __floats2bfloat162_rn(a, b);
    float2 hf = __bfloat1622float2(hb);
    __nv_bfloat162 lb = __floats2bfloat162_rn(a - hf.x, b - hf.y);
    h = *reinterpret_cast<uint32_t*>(&hb);
    l = *reinterpret_cast<uint32_t*>(&lb);
}

// ---------------------------------------------------------------------------
// cp.async-pipelined HMMA GEMM with block-shared B conversion.
// partial[sp][t][o] = sum_k rec[t][k] * w[o][k]; bf16 3-product, fp32 accum.
// ---------------------------------------------------------------------------
__global__ void __launch_bounds__(256, 2)
gemm_pipe(const float* __restrict__ rec, const float* __restrict__ wgt)
{
    extern __shared__ __align__(128) char smem[];
    const uint32_t sbase = smem_u32(smem);

    const int tid = threadIdx.x;
    const int wid = tid >> 5;
    const int lid = tid & 31;
    const int g   = lid >> 2;
    const int tig = lid & 3;
    const int ot  = blockIdx.x;        // 0..3
    const int sp  = blockIdx.y;        // 0..73
    const int obase = ot * 128;

    const int s_begin = sp * SBASE + (sp < SREM ? sp : SREM);
    const int s_count = SBASE + (sp < SREM ? 1 : 0);

    // ---- staging maps ----
    const float* asrc[4];
    uint32_t adst[4];
#pragma unroll
    for (int j = 0; j < 4; j++) {
        const int i = tid + 256 * j;
        const int arow = i >> 3, achk = i & 7;
        asrc[j] = wgt + (size_t)(obase + arow) * KD + achk * 4;
        adst[j] = sbase + (uint32_t)(arow * A_STRIDE + achk * 16);
    }
    const int brow = tid >> 3, bchk = tid & 7;
    const float* bsrc = rec + (size_t)brow * KD + bchk * 4;
    const uint32_t bdst = sbase + (uint32_t)(BF_OFF + brow * BF_STRIDE + bchk * 16);

#define ISSUE(S)                                                              \
    {   const uint32_t so = (uint32_t)((S) % 3) * STAGE_BYTES;                 \
        const size_t ko = (size_t)(s_begin + (S)) * KSLAB;                     \
        _Pragma("unroll") for (int j = 0; j < 4; j++)                          \
            cp16(adst[j] + so, asrc[j] + ko);                                  \
        cp16(bdst + so, bsrc + ko); }

    // ---- shared B convert map (thread: row=tid>>3, 4 k at kq=tid&7) ----
    const uint32_t cvt_src = sbase + (uint32_t)(BF_OFF + brow * BF_STRIDE + bchk * 16);
    const uint32_t cvt_h   = sbase + (uint32_t)(BH_OFF + brow * BB_STRIDE + bchk * 8);
    const uint32_t cvt_l   = sbase + (uint32_t)(BL_OFF + brow * BB_STRIDE + bchk * 8);

    // ---- compute lane addresses ----
    const uint32_t a0b = sbase + (uint32_t)((wid * 16 + g) * A_STRIDE + tig * 8);
    const uint32_t a1b = a0b + 8 * A_STRIDE;
    const uint32_t bb  = sbase + (uint32_t)(BH_OFF + (lid & 7) * BB_STRIDE
                          + ((lid >> 3) & 1) * 16);

    float acc[4][4];
#pragma unroll
    for (int nt = 0; nt < 4; nt++)
#pragma unroll
        for (int i = 0; i < 4; i++) acc[nt][i] = 0.0f;

    ISSUE(0) asm volatile("cp.async.commit_group;" ::: "memory");
    ISSUE(1) asm volatile("cp.async.commit_group;" ::: "memory");

    for (int s = 0; s < s_count; s++) {
        asm volatile("cp.async.wait_group 1;" ::: "memory");
        __syncthreads();
        if (s + 2 < s_count) ISSUE(s + 2)
        asm volatile("cp.async.commit_group;" ::: "memory");

        const uint32_t so = (uint32_t)(s % 3) * STAGE_BYTES;

        // block-shared B convert: fp32 [32][32] -> bf16 hi/lo tiles
        {
            const float4 v = lds128(cvt_src + so);
            uint32_t h0, l0, h1, l1;
            cvt2(v.x, v.y, h0, l0);
            cvt2(v.z, v.w, h1, l1);
            sts64(cvt_h + so, h0, h1);
            sts64(cvt_l + so, l0, l1);
        }
        __syncthreads();

#pragma unroll
        for (int ks = 0; ks < 2; ks++) {
            const uint32_t ao = so + ks * 64;
            const float2 f0 = lds64(a0b + ao);
            const float2 f1 = lds64(a1b + ao);
            const float2 f2 = lds64(a0b + ao + 32);
            const float2 f3 = lds64(a1b + ao + 32);
            uint32_t Ah[4], Al[4];
            cvt2(f0.x, f0.y, Ah[0], Al[0]);
            cvt2(f1.x, f1.y, Ah[1], Al[1]);
            cvt2(f2.x, f2.y, Ah[2], Al[2]);
            cvt2(f3.x, f3.y, Ah[3], Al[3]);
            const uint32_t bo = bb + so + ks * 32;
#pragma unroll
            for (int nt = 0; nt < 4; nt++) {
                uint32_t Bh[2], Bl[2];
                ldsm_x2(Bh, bo + nt * (8 * BB_STRIDE));
                ldsm_x2(Bl, bo + nt * (8 * BB_STRIDE) + (BL_OFF - BH_OFF));
                mma_bf16(acc[nt], Ah, Bh);   // hh
                mma_bf16(acc[nt], Ah, Bl);   // hl
                mma_bf16(acc[nt], Al, Bh);   // lh
            }
        }
    }

    // epilogue
    const int orow = obase + wid * 16 + g;
#pragma unroll
    for (int nt = 0; nt < 4; nt++)
#pragma unroll
        for (int c = 0; c < 4; c++) {
            const int o = orow + ((c >> 1) ? 8 : 0);
            const int t = nt * 8 + 2 * tig + (c & 1);
            g_partial[((size_t)sp * T_DIM + t) * K2 + o] = acc[nt][c];
        }
}

// ---------------------------------------------------------------------------
// deterministic split-K reduction
// ---------------------------------------------------------------------------
__global__ void __launch_bounds__(512) reduce_kernel()
{
    const int t = blockIdx.x;
    const int o = threadIdx.x;
    const size_t stride = (size_t)T_DIM * K2;
    const size_t idx = (size_t)t * K2 + o;
    float s = 0.0f;
#pragma unroll
    for (int sp = 0; sp < KSPLIT; sp++)
        s += g_partial[(size_t)sp * stride + idx];
    g_dot[t * K2 + o] = s;
}

// ---------------------------------------------------------------------------
// post: threshold -> first-spike -> totals -> 8-round k-WTA (shuffle argmax)
// ---------------------------------------------------------------------------
__global__ void __launch_bounds__(512) post_kernel(float* __restrict__ outp)
{
    const int o    = threadIdx.x;
    const int lane = o & 31;
    const int w    = o >> 5;

    unsigned mask = 0;
    int cnt = 0;
#pragma unroll
    for (int t = 0; t < T_DIM; t++) {
        const float v = g_dot[t * K2 + o];
        if (v >= THRESH) { cnt++; mask |= (1u << t); }
    }
    int first = T_DIM - cnt;
    if (first > T_DIM - 1) first = T_DIM - 1;
    const float fv    = g_dot[first * K2 + o];
    const float value = (fv < THRESH) ? 0.0f : fv;
    const float cand  = (cnt > 0) ? value : 0.0f;

    __shared__ float wmaxf[16];
    __shared__ unsigned long long wmax[16];
    __shared__ int s_win;

    float m = cand;
#pragma unroll
    for (int off = 16; off; off >>= 1)
        m = fmaxf(m, __shfl_xor_sync(0xffffffffu, m, off));
    if (lane == 0) wmaxf[w] = m;
    __syncthreads();
    if (o == 0) {
        float mm = wmaxf[0];
#pragma unroll
        for (int i = 1; i < 16; i++) mm = fmaxf(mm, wmaxf[i]);
        wmaxf[0] = mm;
    }
    __syncthreads();
    const float voff = wmaxf[0] * (float)T_DIM;

    float tot = (cnt > 0) ? (float)cnt * (value + voff) : 0.0f;
    bool sel = false;

    for (int r = 0; r < 8; r++) {
        unsigned long long pk =
            ((unsigned long long)__float_as_uint(tot) << 32)
            | (unsigned)(K2 - 1 - o);
#pragma unroll
        for (int off = 16; off; off >>= 1) {
            unsigned long long other = __shfl_xor_sync(0xffffffffu, pk, off);
            if (other > pk) pk = other;
        }
        if (lane == 0) wmax[w] = pk;
        __syncthreads();
        if (o == 0) {
            unsigned long long best = wmax[0];
#pragma unroll
            for (int i = 1; i < 16; i++) if (wmax[i] > best) best = wmax[i];
            s_win = (K2 - 1) - (int)(unsigned)(best & 0xffffffffULL);
        }
        __syncthreads();
        if (o == s_win) {
            if (tot != 0.0f) sel = true;
            tot = 0.0f;
        }
        __syncthreads();
    }

#pragma unroll
    for (int t = 0; t < T_DIM; t++) {
        outp[t * K2 + o] = (sel && ((mask >> t) & 1u)) ? 1.0f : 0.0f;
    }
}

// ---------------------------------------------------------------------------
extern "C" void kernel_launch(void* const* d_in, const int* in_sizes, int n_in,
                              void* d_out, int out_size)
{
    const float* rec = (const float*)d_in[0];   // (32,1,64,4096)
    const float* wgt = (const float*)d_in[1];   // (512,1,64,4096)
    if (n_in >= 2 && in_sizes[0] > in_sizes[1]) {
        const float* tmp = rec; rec = wgt; wgt = tmp;
    }
    float* outp = (float*)d_out;

    cudaFuncSetAttribute(gemm_pipe, cudaFuncAttributeMaxDynamicSharedMemorySize,
                         SMEM_TOTAL);

    gemm_pipe<<<dim3(4, KSPLIT), 256, SMEM_TOTAL>>>(rec, wgt);
    reduce_kernel<<<T_DIM, K2>>>();
    post_kernel<<<1, K2>>>(outp);
}

// round 10
// speedup vs baseline: 1.0774x; 1.0621x over previous
#include <cuda_runtime.h>
#include <cuda_bf16.h>
#include <cstdint>
#include <cstddef>

#define T_DIM  32
#define K2     512
#define KD     262144
#define THRESH 0.2f

#define KSPLIT 74
#define KSLAB  32                          // fp32 k per pipeline stage
#define NSLAB_TOT (KD / KSLAB)             // 8192
#define SBASE (NSLAB_TOT / KSPLIT)         // 110
#define SREM  (NSLAB_TOT - SBASE * KSPLIT) // 52

#define STAGES   4
#define A_STRIDE 144                       // 128B data + 16B pad per W row
#define A_BYTES  (128 * A_STRIDE)          // 18432
#define BF_OFF   A_BYTES                   // B fp32 staging: 32 x 144B
#define BF_STRIDE 144
#define BH_OFF   (BF_OFF + 32 * BF_STRIDE)
#define BB_STRIDE 80                       // bf16 rows: 64B data + 16B pad
#define BL_OFF   (BH_OFF + 32 * BB_STRIDE)
#define STAGE_BYTES (BL_OFF + 32 * BB_STRIDE)   // 28160
#define SMEM_TOTAL  (STAGES * STAGE_BYTES)      // 112640

__device__ float g_partial[(size_t)KSPLIT * T_DIM * K2];
__device__ float g_dot[T_DIM * K2];

// ---------------- helpers ----------------
__device__ __forceinline__ uint32_t smem_u32(const void* p) {
    uint32_t a;
    asm("{ .reg .u64 t; cvta.to.shared.u64 t, %1; cvt.u32.u64 %0, t; }"
        : "=r"(a) : "l"(p));
    return a;
}
__device__ __forceinline__ void cp16(uint32_t dst, const void* src) {
    asm volatile("cp.async.cg.shared.global [%0], [%1], 16;"
                 :: "r"(dst), "l"(src) : "memory");
}
__device__ __forceinline__ float2 lds64(uint32_t a) {
    float2 v;
    asm volatile("ld.shared.v2.f32 {%0,%1}, [%2];"
                 : "=f"(v.x), "=f"(v.y) : "r"(a));
    return v;
}
__device__ __forceinline__ float4 lds128(uint32_t a) {
    float4 v;
    asm volatile("ld.shared.v4.f32 {%0,%1,%2,%3}, [%4];"
                 : "=f"(v.x), "=f"(v.y), "=f"(v.z), "=f"(v.w) : "r"(a));
    return v;
}
__device__ __forceinline__ void sts64(uint32_t a, uint32_t x, uint32_t y) {
    asm volatile("st.shared.v2.b32 [%0], {%1,%2};" :: "r"(a), "r"(x), "r"(y)
                 : "memory");
}
__device__ __forceinline__ void ldsm_x2(uint32_t* r, uint32_t addr) {
    asm volatile("ldmatrix.sync.aligned.m8n8.x2.shared.b16 {%0,%1}, [%2];"
                 : "=r"(r[0]), "=r"(r[1]) : "r"(addr));
}
__device__ __forceinline__ void mma_bf16(float* c, const uint32_t* a, const uint32_t* b) {
    asm volatile("mma.sync.aligned.m16n8k16.row.col.f32.bf16.bf16.f32 "
                 "{%0,%1,%2,%3}, {%4,%5,%6,%7}, {%8,%9}, {%0,%1,%2,%3};"
                 : "+f"(c[0]), "+f"(c[1]), "+f"(c[2]), "+f"(c[3])
                 : "r"(a[0]), "r"(a[1]), "r"(a[2]), "r"(a[3]),
                   "r"(b[0]), "r"(b[1]));
}
__device__ __forceinline__ void cvt2(float a, float b, uint32_t& h, uint32_t& l) {
    __nv_bfloat162 hb = __floats2bfloat162_rn(a, b);
    float2 hf = __bfloat1622float2(hb);
    __nv_bfloat162 lb = __floats2bfloat162_rn(a - hf.x, b - hf.y);
    h = *reinterpret_cast<uint32_t*>(&hb);
    l = *reinterpret_cast<uint32_t*>(&lb);
}

// ---------------------------------------------------------------------------
// cp.async-pipelined HMMA GEMM, 4-stage ring, 1 barrier/slab.
// partial[sp][t][o] = sum_k rec[t][k] * w[o][k]; bf16 3-product, fp32 accum.
// ---------------------------------------------------------------------------
__global__ void __launch_bounds__(256, 2)
gemm_pipe(const float* __restrict__ rec, const float* __restrict__ wgt)
{
    extern __shared__ __align__(128) char smem[];
    const uint32_t sbase = smem_u32(smem);

    const int tid = threadIdx.x;
    const int wid = tid >> 5;
    const int lid = tid & 31;
    const int g   = lid >> 2;
    const int tig = lid & 3;
    const int ot  = blockIdx.x;        // 0..3
    const int sp  = blockIdx.y;        // 0..73
    const int obase = ot * 128;

    const int s_begin = sp * SBASE + (sp < SREM ? sp : SREM);
    const int s_count = SBASE + (sp < SREM ? 1 : 0);

    // ---- staging maps ----
    const float* asrc[4];
    uint32_t adst[4];
#pragma unroll
    for (int j = 0; j < 4; j++) {
        const int i = tid + 256 * j;
        const int arow = i >> 3, achk = i & 7;
        asrc[j] = wgt + (size_t)(obase + arow) * KD + achk * 4;
        adst[j] = sbase + (uint32_t)(arow * A_STRIDE + achk * 16);
    }
    const int brow = tid >> 3, bchk = tid & 7;
    const float* bsrc = rec + (size_t)brow * KD + bchk * 4;
    const uint32_t bdst = sbase + (uint32_t)(BF_OFF + brow * BF_STRIDE + bchk * 16);

#define ISSUE(S)                                                              \
    {   const uint32_t so = (uint32_t)((S) & 3) * STAGE_BYTES;                 \
        const size_t ko = (size_t)(s_begin + (S)) * KSLAB;                     \
        _Pragma("unroll") for (int j = 0; j < 4; j++)                          \
            cp16(adst[j] + so, asrc[j] + ko);                                  \
        cp16(bdst + so, bsrc + ko); }

    // ---- shared B convert map (reads the thread's OWN cp.async bytes) ----
    const uint32_t cvt_src = bdst;
    const uint32_t cvt_h   = sbase + (uint32_t)(BH_OFF + brow * BB_STRIDE + bchk * 8);
    const uint32_t cvt_l   = sbase + (uint32_t)(BL_OFF + brow * BB_STRIDE + bchk * 8);

    // ---- compute lane addresses ----
    const uint32_t a0b = sbase + (uint32_t)((wid * 16 + g) * A_STRIDE + tig * 8);
    const uint32_t a1b = a0b + 8 * A_STRIDE;
    const uint32_t bb  = sbase + (uint32_t)(BH_OFF + (lid & 7) * BB_STRIDE
                          + ((lid >> 3) & 1) * 16);

    float acc[4][4];
#pragma unroll
    for (int nt = 0; nt < 4; nt++)
#pragma unroll
        for (int i = 0; i < 4; i++) acc[nt][i] = 0.0f;

    ISSUE(0) asm volatile("cp.async.commit_group;" ::: "memory");
    ISSUE(1) asm volatile("cp.async.commit_group;" ::: "memory");
    ISSUE(2) asm volatile("cp.async.commit_group;" ::: "memory");

    for (int s = 0; s < s_count; s++) {
        asm volatile("cp.async.wait_group 2;" ::: "memory");

        const uint32_t so = (uint32_t)(s & 3) * STAGE_BYTES;

        // convert own B bytes (visible to this thread after wait_group)
        {
            const float4 v = lds128(cvt_src + so);
            uint32_t h0, l0, h1, l1;
            cvt2(v.x, v.y, h0, l0);
            cvt2(v.z, v.w, h1, l1);
            sts64(cvt_h + so, h0, h1);
            sts64(cvt_l + so, l0, l1);
        }
        __syncthreads();   // publishes A + converted B; frees ring slot (s-1)&3

        if (s + 3 < s_count) ISSUE(s + 3)
        asm volatile("cp.async.commit_group;" ::: "memory");

#pragma unroll
        for (int ks = 0; ks < 2; ks++) {
            const uint32_t ao = so + ks * 64;
            const float2 f0 = lds64(a0b + ao);
            const float2 f1 = lds64(a1b + ao);
            const float2 f2 = lds64(a0b + ao + 32);
            const float2 f3 = lds64(a1b + ao + 32);
            uint32_t Ah[4], Al[4];
            cvt2(f0.x, f0.y, Ah[0], Al[0]);
            cvt2(f1.x, f1.y, Ah[1], Al[1]);
            cvt2(f2.x, f2.y, Ah[2], Al[2]);
            cvt2(f3.x, f3.y, Ah[3], Al[3]);
            const uint32_t bo = bb + so + ks * 32;
#pragma unroll
            for (int nt = 0; nt < 4; nt++) {
                uint32_t Bh[2], Bl[2];
                ldsm_x2(Bh, bo + nt * (8 * BB_STRIDE));
                ldsm_x2(Bl, bo + nt * (8 * BB_STRIDE) + (BL_OFF - BH_OFF));
                mma_bf16(acc[nt], Ah, Bh);   // hh
                mma_bf16(acc[nt], Ah, Bl);   // hl
                mma_bf16(acc[nt], Al, Bh);   // lh
            }
        }
    }

    // epilogue
    const int orow = obase + wid * 16 + g;
#pragma unroll
    for (int nt = 0; nt < 4; nt++)
#pragma unroll
        for (int c = 0; c < 4; c++) {
            const int o = orow + ((c >> 1) ? 8 : 0);
            const int t = nt * 8 + 2 * tig + (c & 1);
            g_partial[((size_t)sp * T_DIM + t) * K2 + o] = acc[nt][c];
        }
}

// ---------------------------------------------------------------------------
// deterministic split-K reduction
// ---------------------------------------------------------------------------
__global__ void __launch_bounds__(512) reduce_kernel()
{
    const int t = blockIdx.x;
    const int o = threadIdx.x;
    const size_t stride = (size_t)T_DIM * K2;
    const size_t idx = (size_t)t * K2 + o;
    float s = 0.0f;
#pragma unroll
    for (int sp = 0; sp < KSPLIT; sp++)
        s += g_partial[(size_t)sp * stride + idx];
    g_dot[t * K2 + o] = s;
}

// ---------------------------------------------------------------------------
// post: threshold -> first-spike -> totals -> 8-round k-WTA (shuffle argmax)
// ---------------------------------------------------------------------------
__global__ void __launch_bounds__(512) post_kernel(float* __restrict__ outp)
{
    const int o    = threadIdx.x;
    const int lane = o & 31;
    const int w    = o >> 5;

    unsigned mask = 0;
    int cnt = 0;
#pragma unroll
    for (int t = 0; t < T_DIM; t++) {
        const float v = g_dot[t * K2 + o];
        if (v >= THRESH) { cnt++; mask |= (1u << t); }
    }
    int first = T_DIM - cnt;
    if (first > T_DIM - 1) first = T_DIM - 1;
    const float fv    = g_dot[first * K2 + o];
    const float value = (fv < THRESH) ? 0.0f : fv;
    const float cand  = (cnt > 0) ? value : 0.0f;

    __shared__ float wmaxf[16];
    __shared__ unsigned long long wmax[16];
    __shared__ int s_win;

    float m = cand;
#pragma unroll
    for (int off = 16; off; off >>= 1)
        m = fmaxf(m, __shfl_xor_sync(0xffffffffu, m, off));
    if (lane == 0) wmaxf[w] = m;
    __syncthreads();
    if (o == 0) {
        float mm = wmaxf[0];
#pragma unroll
        for (int i = 1; i < 16; i++) mm = fmaxf(mm, wmaxf[i]);
        wmaxf[0] = mm;
    }
    __syncthreads();
    const float voff = wmaxf[0] * (float)T_DIM;

    float tot = (cnt > 0) ? (float)cnt * (value + voff) : 0.0f;
    bool sel = false;

    for (int r = 0; r < 8; r++) {
        unsigned long long pk =
            ((unsigned long long)__float_as_uint(tot) << 32)
            | (unsigned)(K2 - 1 - o);
#pragma unroll
        for (int off = 16; off; off >>= 1) {
            unsigned long long other = __shfl_xor_sync(0xffffffffu, pk, off);
            if (other > pk) pk = other;
        }
        if (lane == 0) wmax[w] = pk;
        __syncthreads();
        if (o == 0) {
            unsigned long long best = wmax[0];
#pragma unroll
            for (int i = 1; i < 16; i++) if (wmax[i] > best) best = wmax[i];
            s_win = (K2 - 1) - (int)(unsigned)(best & 0xffffffffULL);
        }
        __syncthreads();
        if (o == s_win) {
            if (tot != 0.0f) sel = true;
            tot = 0.0f;
        }
        __syncthreads();
    }

#pragma unroll
    for (int t = 0; t < T_DIM; t++) {
        outp[t * K2 + o] = (sel && ((mask >> t) & 1u)) ? 1.0f : 0.0f;
    }
}

// ---------------------------------------------------------------------------
extern "C" void kernel_launch(void* const* d_in, const int* in_sizes, int n_in,
                              void* d_out, int out_size)
{
    const float* rec = (const float*)d_in[0];   // (32,1,64,4096)
    const float* wgt = (const float*)d_in[1];   // (512,1,64,4096)
    if (n_in >= 2 && in_sizes[0] > in_sizes[1]) {
        const float* tmp = rec; rec = wgt; wgt = tmp;
    }
    float* outp = (float*)d_out;

    cudaFuncSetAttribute(gemm_pipe, cudaFuncAttributeMaxDynamicSharedMemorySize,
                         SMEM_TOTAL);

    gemm_pipe<<<dim3(4, KSPLIT), 256, SMEM_TOTAL>>>(rec, wgt);
    reduce_kernel<<<T_DIM, K2>>>();
    post_kernel<<<1, K2>>>(outp);
}

// round 11
// speedup vs baseline: 1.1464x; 1.0640x over previous
#include <cuda_runtime.h>
#include <cuda_bf16.h>
#include <cstdint>
#include <cstddef>

#define T_DIM  32
#define K2     512
#define KD     262144
#define THRESH 0.2f

#define KSPLIT 111                         // grid 4*111 = 444 = 148 SMs * 3
#define KSLAB  32                          // fp32 k per pipeline stage
#define NSLAB_TOT (KD / KSLAB)             // 8192
#define SBASE (NSLAB_TOT / KSPLIT)         // 73
#define SREM  (NSLAB_TOT - SBASE * KSPLIT) // 89

#define STAGES   3
#define A_STRIDE 144                       // 128B data + 16B pad per W row
#define A_BYTES  (128 * A_STRIDE)          // 18432
#define BH_OFF   A_BYTES
#define BB_STRIDE 80                       // bf16 rows: 64B data + 16B pad
#define BL_OFF   (BH_OFF + 32 * BB_STRIDE)
#define STAGE_BYTES (BL_OFF + 32 * BB_STRIDE)   // 23552
#define SMEM_TOTAL  (STAGES * STAGE_BYTES)      // 70656 (x3 CTAs = 212KB)

__device__ float g_partial[(size_t)KSPLIT * T_DIM * K2];
__device__ float g_dot[T_DIM * K2];

// ---------------- helpers ----------------
__device__ __forceinline__ uint32_t smem_u32(const void* p) {
    uint32_t a;
    asm("{ .reg .u64 t; cvta.to.shared.u64 t, %1; cvt.u32.u64 %0, t; }"
        : "=r"(a) : "l"(p));
    return a;
}
__device__ __forceinline__ void cp16(uint32_t dst, const void* src) {
    asm volatile("cp.async.cg.shared.global [%0], [%1], 16;"
                 :: "r"(dst), "l"(src) : "memory");
}
__device__ __forceinline__ float2 lds64(uint32_t a) {
    float2 v;
    asm volatile("ld.shared.v2.f32 {%0,%1}, [%2];"
                 : "=f"(v.x), "=f"(v.y) : "r"(a));
    return v;
}
__device__ __forceinline__ void sts64(uint32_t a, uint32_t x, uint32_t y) {
    asm volatile("st.shared.v2.b32 [%0], {%1,%2};" :: "r"(a), "r"(x), "r"(y)
                 : "memory");
}
__device__ __forceinline__ void ldsm_x2(uint32_t* r, uint32_t addr) {
    asm volatile("ldmatrix.sync.aligned.m8n8.x2.shared.b16 {%0,%1}, [%2];"
                 : "=r"(r[0]), "=r"(r[1]) : "r"(addr));
}
__device__ __forceinline__ void mma_bf16(float* c, const uint32_t* a, const uint32_t* b) {
    asm volatile("mma.sync.aligned.m16n8k16.row.col.f32.bf16.bf16.f32 "
                 "{%0,%1,%2,%3}, {%4,%5,%6,%7}, {%8,%9}, {%0,%1,%2,%3};"
                 : "+f"(c[0]), "+f"(c[1]), "+f"(c[2]), "+f"(c[3])
                 : "r"(a[0]), "r"(a[1]), "r"(a[2]), "r"(a[3]),
                   "r"(b[0]), "r"(b[1]));
}
__device__ __forceinline__ void cvt2(float a, float b, uint32_t& h, uint32_t& l) {
    __nv_bfloat162 hb = __floats2bfloat162_rn(a, b);
    float2 hf = __bfloat1622float2(hb);
    __nv_bfloat162 lb = __floats2bfloat162_rn(a - hf.x, b - hf.y);
    h = *reinterpret_cast<uint32_t*>(&hb);
    l = *reinterpret_cast<uint32_t*>(&lb);
}

// ---------------------------------------------------------------------------
// cp.async-pipelined HMMA GEMM, 3-stage ring, 3 CTAs/SM, 1 barrier/slab.
// A (W) staged fp32 via cp.async; B (rec) LDG->reg->block convert->bf16 smem.
// bf16 3-product (hh+hl+lh), fp32 accum. warp = 16 o x 32 t.
// ---------------------------------------------------------------------------
__global__ void __launch_bounds__(256, 3)
gemm_pipe(const float* __restrict__ rec, const float* __restrict__ wgt)
{
    extern __shared__ __align__(128) char smem[];
    const uint32_t sbase = smem_u32(smem);

    const int tid = threadIdx.x;
    const int wid = tid >> 5;
    const int lid = tid & 31;
    const int g   = lid >> 2;
    const int tig = lid & 3;
    const int ot  = blockIdx.x;        // 0..3
    const int sp  = blockIdx.y;        // 0..110
    const int obase = ot * 128;

    const int s_begin = sp * SBASE + (sp < SREM ? sp : SREM);
    const int s_count = SBASE + (sp < SREM ? 1 : 0);

    // ---- A staging map: thread covers rows (tid>>3)+32j, chunk tid&7 ----
    const float* asrc0 = wgt + (size_t)(obase + (tid >> 3)) * KD
                         + (size_t)s_begin * KSLAB + (tid & 7) * 4;
    const uint32_t adst0 = sbase + (uint32_t)((tid >> 3) * A_STRIDE + (tid & 7) * 16);

#define ISSUE(S)                                                              \
    {   const uint32_t so = (uint32_t)((S) % 3) * STAGE_BYTES;                 \
        const size_t ko = (size_t)(S) * KSLAB;                                 \
        cp16(adst0 + so,                    asrc0 + ko);                       \
        cp16(adst0 + so + 32 * A_STRIDE,    asrc0 + ko + (size_t)32 * KD);     \
        cp16(adst0 + so + 64 * A_STRIDE,    asrc0 + ko + (size_t)64 * KD);     \
        cp16(adst0 + so + 96 * A_STRIDE,    asrc0 + ko + (size_t)96 * KD); }

    // ---- B map: thread covers row tid>>3, chunk tid&7 (4 floats) ----
    const int brow = tid >> 3, bchk = tid & 7;
    const float* bsrc = rec + (size_t)brow * KD
                        + (size_t)s_begin * KSLAB + bchk * 4;
    const uint32_t cvt_h = sbase + (uint32_t)(BH_OFF + brow * BB_STRIDE + bchk * 8);
    const uint32_t cvt_l = sbase + (uint32_t)(BL_OFF + brow * BB_STRIDE + bchk * 8);

    // ---- compute lane addresses ----
    const uint32_t a0b = sbase + (uint32_t)((wid * 16 + g) * A_STRIDE + tig * 8);
    const uint32_t a1b = a0b + 8 * A_STRIDE;
    const uint32_t bb  = sbase + (uint32_t)(BH_OFF + (lid & 7) * BB_STRIDE
                          + ((lid >> 3) & 1) * 16);

    float acc[4][4];
#pragma unroll
    for (int nt = 0; nt < 4; nt++)
#pragma unroll
        for (int i = 0; i < 4; i++) acc[nt][i] = 0.0f;

    // prologue
    ISSUE(0) asm volatile("cp.async.commit_group;" ::: "memory");
    ISSUE(1) asm volatile("cp.async.commit_group;" ::: "memory");
    float4 breg = *reinterpret_cast<const float4*>(bsrc);

    for (int s = 0; s < s_count; s++) {
        asm volatile("cp.async.wait_group 1;" ::: "memory");

        const uint32_t so = (uint32_t)(s % 3) * STAGE_BYTES;

        // block-shared B convert from registers into bf16 hi/lo tiles
        {
            uint32_t h0, l0, h1, l1;
            cvt2(breg.x, breg.y, h0, l0);
            cvt2(breg.z, breg.w, h1, l1);
            sts64(cvt_h + so, h0, h1);
            sts64(cvt_l + so, l0, l1);
        }
        __syncthreads();   // publishes A(s) + converted B(s); frees slot (s-1)%3

        if (s + 2 < s_count) ISSUE(s + 2)
        asm volatile("cp.async.commit_group;" ::: "memory");
        if (s + 1 < s_count)
            breg = *reinterpret_cast<const float4*>(bsrc + (size_t)(s + 1) * KSLAB);

#pragma unroll
        for (int ks = 0; ks < 2; ks++) {
            const uint32_t ao = so + ks * 64;
            const float2 f0 = lds64(a0b + ao);
            const float2 f1 = lds64(a1b + ao);
            const float2 f2 = lds64(a0b + ao + 32);
            const float2 f3 = lds64(a1b + ao + 32);
            uint32_t Ah[4], Al[4];
            cvt2(f0.x, f0.y, Ah[0], Al[0]);
            cvt2(f1.x, f1.y, Ah[1], Al[1]);
            cvt2(f2.x, f2.y, Ah[2], Al[2]);
            cvt2(f3.x, f3.y, Ah[3], Al[3]);
            const uint32_t bo = bb + so + ks * 32;
#pragma unroll
            for (int nt = 0; nt < 4; nt++) {
                uint32_t Bh[2], Bl[2];
                ldsm_x2(Bh, bo + nt * (8 * BB_STRIDE));
                ldsm_x2(Bl, bo + nt * (8 * BB_STRIDE) + (BL_OFF - BH_OFF));
                mma_bf16(acc[nt], Ah, Bh);   // hh
                mma_bf16(acc[nt], Ah, Bl);   // hl
                mma_bf16(acc[nt], Al, Bh);   // lh
            }
        }
    }

    // epilogue
    const int orow = obase + wid * 16 + g;
#pragma unroll
    for (int nt = 0; nt < 4; nt++)
#pragma unroll
        for (int c = 0; c < 4; c++) {
            const int o = orow + ((c >> 1) ? 8 : 0);
            const int t = nt * 8 + 2 * tig + (c & 1);
            g_partial[((size_t)sp * T_DIM + t) * K2 + o] = acc[nt][c];
        }
}

// ---------------------------------------------------------------------------
// deterministic split-K reduction
// ---------------------------------------------------------------------------
__global__ void __launch_bounds__(512) reduce_kernel()
{
    const int t = blockIdx.x;
    const int o = threadIdx.x;
    const size_t stride = (size_t)T_DIM * K2;
    const size_t idx = (size_t)t * K2 + o;
    float s = 0.0f;
#pragma unroll
    for (int sp = 0; sp < KSPLIT; sp++)
        s += g_partial[(size_t)sp * stride + idx];
    g_dot[t * K2 + o] = s;
}

// ---------------------------------------------------------------------------
// post: threshold -> first-spike -> totals -> 8-round k-WTA (shuffle argmax)
// ---------------------------------------------------------------------------
__global__ void __launch_bounds__(512) post_kernel(float* __restrict__ outp)
{
    const int o    = threadIdx.x;
    const int lane = o & 31;
    const int w    = o >> 5;

    unsigned mask = 0;
    int cnt = 0;
#pragma unroll
    for (int t = 0; t < T_DIM; t++) {
        const float v = g_dot[t * K2 + o];
        if (v >= THRESH) { cnt++; mask |= (1u << t); }
    }
    int first = T_DIM - cnt;
    if (first > T_DIM - 1) first = T_DIM - 1;
    const float fv    = g_dot[first * K2 + o];
    const float value = (fv < THRESH) ? 0.0f : fv;
    const float cand  = (cnt > 0) ? value : 0.0f;

    __shared__ float wmaxf[16];
    __shared__ unsigned long long wmax[16];
    __shared__ int s_win;

    float m = cand;
#pragma unroll
    for (int off = 16; off; off >>= 1)
        m = fmaxf(m, __shfl_xor_sync(0xffffffffu, m, off));
    if (lane == 0) wmaxf[w] = m;
    __syncthreads();
    if (o == 0) {
        float mm = wmaxf[0];
#pragma unroll
        for (int i = 1; i < 16; i++) mm = fmaxf(mm, wmaxf[i]);
        wmaxf[0] = mm;
    }
    __syncthreads();
    const float voff = wmaxf[0] * (float)T_DIM;

    float tot = (cnt > 0) ? (float)cnt * (value + voff) : 0.0f;
    bool sel = false;

    for (int r = 0; r < 8; r++) {
        unsigned long long pk =
            ((unsigned long long)__float_as_uint(tot) << 32)
            | (unsigned)(K2 - 1 - o);
#pragma unroll
        for (int off = 16; off; off >>= 1) {
            unsigned long long other = __shfl_xor_sync(0xffffffffu, pk, off);
            if (other > pk) pk = other;
        }
        if (lane == 0) wmax[w] = pk;
        __syncthreads();
        if (o == 0) {
            unsigned long long best = wmax[0];
#pragma unroll
            for (int i = 1; i < 16; i++) if (wmax[i] > best) best = wmax[i];
            s_win = (K2 - 1) - (int)(unsigned)(best & 0xffffffffULL);
        }
        __syncthreads();
        if (o == s_win) {
            if (tot != 0.0f) sel = true;
            tot = 0.0f;
        }
        __syncthreads();
    }

#pragma unroll
    for (int t = 0; t < T_DIM; t++) {
        outp[t * K2 + o] = (sel && ((mask >> t) & 1u)) ? 1.0f : 0.0f;
    }
}

// ---------------------------------------------------------------------------
extern "C" void kernel_launch(void* const* d_in, const int* in_sizes, int n_in,
                              void* d_out, int out_size)
{
    const float* rec = (const float*)d_in[0];   // (32,1,64,4096)
    const float* wgt = (const float*)d_in[1];   // (512,1,64,4096)
    if (n_in >= 2 && in_sizes[0] > in_sizes[1]) {
        const float* tmp = rec; rec = wgt; wgt = tmp;
    }
    float* outp = (float*)d_out;

    cudaFuncSetAttribute(gemm_pipe, cudaFuncAttributeMaxDynamicSharedMemorySize,
                         SMEM_TOTAL);

    gemm_pipe<<<dim3(4, KSPLIT), 256, SMEM_TOTAL>>>(rec, wgt);
    reduce_kernel<<<T_DIM, K2>>>();
    post_kernel<<<1, K2>>>(outp);
}

// round 12
// speedup vs baseline: 1.1862x; 1.0347x over previous
#include <cuda_runtime.h>
#include <cuda_bf16.h>
#include <cstdint>
#include <cstddef>

#define T_DIM  32
#define K2     512
#define KD     262144
#define THRESH 0.2f

#define KSPLIT 148                         // grid 4*148 = 592 = 148 SMs * 4
#define KSLAB  32                          // fp32 k per pipeline stage
#define NSLAB_TOT (KD / KSLAB)             // 8192
#define SBASE (NSLAB_TOT / KSPLIT)         // 55
#define SREM  (NSLAB_TOT - SBASE * KSPLIT) // 52

#define STAGES   2
#define A_STRIDE 144                       // 128B data + 16B pad per W row
#define A_BYTES  (128 * A_STRIDE)          // 18432
#define BH_OFF   A_BYTES
#define BB_STRIDE 80                       // bf16 rows: 64B data + 16B pad
#define BL_OFF   (BH_OFF + 32 * BB_STRIDE)
#define STAGE_BYTES (BL_OFF + 32 * BB_STRIDE)   // 23552
#define SMEM_TOTAL  (STAGES * STAGE_BYTES)      // 47104 (x4 CTAs = 188KB)

__device__ float g_partial[(size_t)KSPLIT * T_DIM * K2];
__device__ float g_dot[T_DIM * K2];

// ---------------- helpers ----------------
__device__ __forceinline__ uint32_t smem_u32(const void* p) {
    uint32_t a;
    asm("{ .reg .u64 t; cvta.to.shared.u64 t, %1; cvt.u32.u64 %0, t; }"
        : "=r"(a) : "l"(p));
    return a;
}
__device__ __forceinline__ void cp16(uint32_t dst, const void* src) {
    asm volatile("cp.async.cg.shared.global [%0], [%1], 16;"
                 :: "r"(dst), "l"(src) : "memory");
}
__device__ __forceinline__ float2 lds64(uint32_t a) {
    float2 v;
    asm volatile("ld.shared.v2.f32 {%0,%1}, [%2];"
                 : "=f"(v.x), "=f"(v.y) : "r"(a));
    return v;
}
__device__ __forceinline__ void sts64(uint32_t a, uint32_t x, uint32_t y) {
    asm volatile("st.shared.v2.b32 [%0], {%1,%2};" :: "r"(a), "r"(x), "r"(y)
                 : "memory");
}
__device__ __forceinline__ void ldsm_x4(uint32_t* r, uint32_t addr) {
    asm volatile("ldmatrix.sync.aligned.m8n8.x4.shared.b16 {%0,%1,%2,%3}, [%4];"
                 : "=r"(r[0]), "=r"(r[1]), "=r"(r[2]), "=r"(r[3]) : "r"(addr));
}
__device__ __forceinline__ void mma_bf16(float* c, const uint32_t* a, const uint32_t* b) {
    asm volatile("mma.sync.aligned.m16n8k16.row.col.f32.bf16.bf16.f32 "
                 "{%0,%1,%2,%3}, {%4,%5,%6,%7}, {%8,%9}, {%0,%1,%2,%3};"
                 : "+f"(c[0]), "+f"(c[1]), "+f"(c[2]), "+f"(c[3])
                 : "r"(a[0]), "r"(a[1]), "r"(a[2]), "r"(a[3]),
                   "r"(b[0]), "r"(b[1]));
}
__device__ __forceinline__ void cvt2(float a, float b, uint32_t& h, uint32_t& l) {
    __nv_bfloat162 hb = __floats2bfloat162_rn(a, b);
    float2 hf = __bfloat1622float2(hb);
    __nv_bfloat162 lb = __floats2bfloat162_rn(a - hf.x, b - hf.y);
    h = *reinterpret_cast<uint32_t*>(&hb);
    l = *reinterpret_cast<uint32_t*>(&lb);
}

// ---------------------------------------------------------------------------
// cp.async-pipelined HMMA GEMM, 2-stage ring, 4 CTAs/SM, 1 barrier/slab.
// A (W) staged fp32 via cp.async; B (rec) LDG->reg->block convert->bf16 smem.
// bf16 3-product (hh+hl+lh), fp32 accum. warp = 16 o x 32 t; ldmatrix.x4 B.
// ---------------------------------------------------------------------------
__global__ void __launch_bounds__(256, 4)
gemm_pipe(const float* __restrict__ rec, const float* __restrict__ wgt)
{
    extern __shared__ __align__(128) char smem[];
    const uint32_t sbase = smem_u32(smem);

    const int tid = threadIdx.x;
    const int wid = tid >> 5;
    const int lid = tid & 31;
    const int g   = lid >> 2;
    const int tig = lid & 3;
    const int ot  = blockIdx.x;        // 0..3
    const int sp  = blockIdx.y;        // 0..147
    const int obase = ot * 128;

    const int s_begin = sp * SBASE + (sp < SREM ? sp : SREM);
    const int s_count = SBASE + (sp < SREM ? 1 : 0);

    // ---- A staging map: thread covers rows (tid>>3)+32j, chunk tid&7 ----
    const float* asrc0 = wgt + (size_t)(obase + (tid >> 3)) * KD
                         + (size_t)s_begin * KSLAB + (tid & 7) * 4;
    const uint32_t adst0 = sbase + (uint32_t)((tid >> 3) * A_STRIDE + (tid & 7) * 16);

#define ISSUE(S)                                                              \
    {   const uint32_t so = (uint32_t)((S) & 1) * STAGE_BYTES;                 \
        const size_t ko = (size_t)(S) * KSLAB;                                 \
        cp16(adst0 + so,                    asrc0 + ko);                       \
        cp16(adst0 + so + 32 * A_STRIDE,    asrc0 + ko + (size_t)32 * KD);     \
        cp16(adst0 + so + 64 * A_STRIDE,    asrc0 + ko + (size_t)64 * KD);     \
        cp16(adst0 + so + 96 * A_STRIDE,    asrc0 + ko + (size_t)96 * KD); }

    // ---- B map: thread covers row tid>>3, chunk tid&7 (4 floats) ----
    const int brow = tid >> 3, bchk = tid & 7;
    const float* bsrc = rec + (size_t)brow * KD
                        + (size_t)s_begin * KSLAB + bchk * 4;
    const uint32_t cvt_h = sbase + (uint32_t)(BH_OFF + brow * BB_STRIDE + bchk * 8);
    const uint32_t cvt_l = sbase + (uint32_t)(BL_OFF + brow * BB_STRIDE + bchk * 8);

    // ---- compute lane addresses ----
    const uint32_t a0b = sbase + (uint32_t)((wid * 16 + g) * A_STRIDE + tig * 8);
    const uint32_t a1b = a0b + 8 * A_STRIDE;
    // ldsm x4 B address: lanes 0-15 -> n-tile nt, lanes 16-31 -> nt+1
    const uint32_t bb  = sbase + (uint32_t)(BH_OFF + (lid & 7) * BB_STRIDE
                          + ((lid >> 3) & 1) * 16
                          + (lid >> 4) * (8 * BB_STRIDE));

    float acc[4][4];
#pragma unroll
    for (int nt = 0; nt < 4; nt++)
#pragma unroll
        for (int i = 0; i < 4; i++) acc[nt][i] = 0.0f;

    // prologue
    ISSUE(0) asm volatile("cp.async.commit_group;" ::: "memory");
    float4 breg = *reinterpret_cast<const float4*>(bsrc);

    for (int s = 0; s < s_count; s++) {
        asm volatile("cp.async.wait_group 0;" ::: "memory");

        const uint32_t so = (uint32_t)(s & 1) * STAGE_BYTES;

        // block-shared B convert from registers into bf16 hi/lo tiles
        {
            uint32_t h0, l0, h1, l1;
            cvt2(breg.x, breg.y, h0, l0);
            cvt2(breg.z, breg.w, h1, l1);
            sts64(cvt_h + so, h0, h1);
            sts64(cvt_l + so, l0, l1);
        }
        __syncthreads();   // publishes A(s) + converted B(s); frees slot s^1

        if (s + 1 < s_count) {
            ISSUE(s + 1)
            breg = *reinterpret_cast<const float4*>(bsrc + (size_t)(s + 1) * KSLAB);
        }
        asm volatile("cp.async.commit_group;" ::: "memory");

#pragma unroll
        for (int ks = 0; ks < 2; ks++) {
            const uint32_t ao = so + ks * 64;
            const float2 f0 = lds64(a0b + ao);
            const float2 f1 = lds64(a1b + ao);
            const float2 f2 = lds64(a0b + ao + 32);
            const float2 f3 = lds64(a1b + ao + 32);
            uint32_t Ah[4], Al[4];
            cvt2(f0.x, f0.y, Ah[0], Al[0]);
            cvt2(f1.x, f1.y, Ah[1], Al[1]);
            cvt2(f2.x, f2.y, Ah[2], Al[2]);
            cvt2(f3.x, f3.y, Ah[3], Al[3]);
            const uint32_t bo = bb + so + ks * 32;
#pragma unroll
            for (int np = 0; np < 2; np++) {
                uint32_t Bh[4], Bl[4];          // two n-tiles per ldsm.x4
                ldsm_x4(Bh, bo + np * (16 * BB_STRIDE));
                ldsm_x4(Bl, bo + np * (16 * BB_STRIDE) + (BL_OFF - BH_OFF));
                mma_bf16(acc[np * 2 + 0], Ah, Bh + 0);
                mma_bf16(acc[np * 2 + 0], Ah, Bl + 0);
                mma_bf16(acc[np * 2 + 0], Al, Bh + 0);
                mma_bf16(acc[np * 2 + 1], Ah, Bh + 2);
                mma_bf16(acc[np * 2 + 1], Ah, Bl + 2);
                mma_bf16(acc[np * 2 + 1], Al, Bh + 2);
            }
        }
    }

    // epilogue
    const int orow = obase + wid * 16 + g;
#pragma unroll
    for (int nt = 0; nt < 4; nt++)
#pragma unroll
        for (int c = 0; c < 4; c++) {
            const int o = orow + ((c >> 1) ? 8 : 0);
            const int t = nt * 8 + 2 * tig + (c & 1);
            g_partial[((size_t)sp * T_DIM + t) * K2 + o] = acc[nt][c];
        }
}

// ---------------------------------------------------------------------------
// deterministic split-K reduction
// ---------------------------------------------------------------------------
__global__ void __launch_bounds__(512) reduce_kernel()
{
    const int t = blockIdx.x;
    const int o = threadIdx.x;
    const size_t stride = (size_t)T_DIM * K2;
    const size_t idx = (size_t)t * K2 + o;
    float s = 0.0f;
#pragma unroll
    for (int sp = 0; sp < KSPLIT; sp++)
        s += g_partial[(size_t)sp * stride + idx];
    g_dot[t * K2 + o] = s;
}

// ---------------------------------------------------------------------------
// post: threshold -> first-spike -> totals -> 8-round k-WTA (shuffle argmax)
// ---------------------------------------------------------------------------
__global__ void __launch_bounds__(512) post_kernel(float* __restrict__ outp)
{
    const int o    = threadIdx.x;
    const int lane = o & 31;
    const int w    = o >> 5;

    unsigned mask = 0;
    int cnt = 0;
#pragma unroll
    for (int t = 0; t < T_DIM; t++) {
        const float v = g_dot[t * K2 + o];
        if (v >= THRESH) { cnt++; mask |= (1u << t); }
    }
    int first = T_DIM - cnt;
    if (first > T_DIM - 1) first = T_DIM - 1;
    const float fv    = g_dot[first * K2 + o];
    const float value = (fv < THRESH) ? 0.0f : fv;
    const float cand  = (cnt > 0) ? value : 0.0f;

    __shared__ float wmaxf[16];
    __shared__ unsigned long long wmax[16];
    __shared__ int s_win;

    float m = cand;
#pragma unroll
    for (int off = 16; off; off >>= 1)
        m = fmaxf(m, __shfl_xor_sync(0xffffffffu, m, off));
    if (lane == 0) wmaxf[w] = m;
    __syncthreads();
    if (o == 0) {
        float mm = wmaxf[0];
#pragma unroll
        for (int i = 1; i < 16; i++) mm = fmaxf(mm, wmaxf[i]);
        wmaxf[0] = mm;
    }
    __syncthreads();
    const float voff = wmaxf[0] * (float)T_DIM;

    float tot = (cnt > 0) ? (float)cnt * (value + voff) : 0.0f;
    bool sel = false;

    for (int r = 0; r < 8; r++) {
        unsigned long long pk =
            ((unsigned long long)__float_as_uint(tot) << 32)
            | (unsigned)(K2 - 1 - o);
#pragma unroll
        for (int off = 16; off; off >>= 1) {
            unsigned long long other = __shfl_xor_sync(0xffffffffu, pk, off);
            if (other > pk) pk = other;
        }
        if (lane == 0) wmax[w] = pk;
        __syncthreads();
        if (o == 0) {
            unsigned long long best = wmax[0];
#pragma unroll
            for (int i = 1; i < 16; i++) if (wmax[i] > best) best = wmax[i];
            s_win = (K2 - 1) - (int)(unsigned)(best & 0xffffffffULL);
        }
        __syncthreads();
        if (o == s_win) {
            if (tot != 0.0f) sel = true;
            tot = 0.0f;
        }
        __syncthreads();
    }

#pragma unroll
    for (int t = 0; t < T_DIM; t++) {
        outp[t * K2 + o] = (sel && ((mask >> t) & 1u)) ? 1.0f : 0.0f;
    }
}

// ---------------------------------------------------------------------------
extern "C" void kernel_launch(void* const* d_in, const int* in_sizes, int n_in,
                              void* d_out, int out_size)
{
    const float* rec = (const float*)d_in[0];   // (32,1,64,4096)
    const float* wgt = (const float*)d_in[1];   // (512,1,64,4096)
    if (n_in >= 2 && in_sizes[0] > in_sizes[1]) {
        const float* tmp = rec; rec = wgt; wgt = tmp;
    }
    float* outp = (float*)d_out;

    cudaFuncSetAttribute(gemm_pipe, cudaFuncAttributeMaxDynamicSharedMemorySize,
                         SMEM_TOTAL);

    gemm_pipe<<<dim3(4, KSPLIT), 256, SMEM_TOTAL>>>(rec, wgt);
    reduce_kernel<<<T_DIM, K2>>>();
    post_kernel<<<1, K2>>>(outp);
}

// round 13
// speedup vs baseline: 1.2095x; 1.0196x over previous
#include <cuda_runtime.h>
#include <cuda_bf16.h>
#include <cstdint>
#include <cstddef>

#define T_DIM  32
#define K2     512
#define KD     262144
#define THRESH 0.2f

#define KSPLIT 148                         // grid 4*148 = 592 = 148 SMs * 4
#define KSLAB  32                          // fp32 k per pipeline stage
#define NSLAB_TOT (KD / KSLAB)             // 8192
#define SBASE (NSLAB_TOT / KSPLIT)         // 55
#define SREM  (NSLAB_TOT - SBASE * KSPLIT) // 52

#define STAGES   2
#define A_STRIDE 160                       // 128B data + 32B pad: conflict-free lds64
#define A_BYTES  (128 * A_STRIDE)          // 20480
#define BH_OFF   A_BYTES
#define BB_STRIDE 80                       // bf16 rows: 64B data + 16B pad
#define BL_OFF   (BH_OFF + 32 * BB_STRIDE)
#define STAGE_BYTES (BL_OFF + 32 * BB_STRIDE)   // 25600
#define SMEM_TOTAL  (STAGES * STAGE_BYTES)      // 51200 (x4 CTAs = 204.8KB)

__device__ float g_partial[(size_t)KSPLIT * T_DIM * K2];
__device__ float g_dot[T_DIM * K2];

// ---------------- helpers ----------------
__device__ __forceinline__ uint32_t smem_u32(const void* p) {
    uint32_t a;
    asm("{ .reg .u64 t; cvta.to.shared.u64 t, %1; cvt.u32.u64 %0, t; }"
        : "=r"(a) : "l"(p));
    return a;
}
__device__ __forceinline__ void cp16(uint32_t dst, const void* src) {
    asm volatile("cp.async.cg.shared.global [%0], [%1], 16;"
                 :: "r"(dst), "l"(src) : "memory");
}
__device__ __forceinline__ float2 lds64(uint32_t a) {
    float2 v;
    asm volatile("ld.shared.v2.f32 {%0,%1}, [%2];"
                 : "=f"(v.x), "=f"(v.y) : "r"(a));
    return v;
}
__device__ __forceinline__ void sts64(uint32_t a, uint32_t x, uint32_t y) {
    asm volatile("st.shared.v2.b32 [%0], {%1,%2};" :: "r"(a), "r"(x), "r"(y)
                 : "memory");
}
__device__ __forceinline__ void ldsm_x4(uint32_t* r, uint32_t addr) {
    asm volatile("ldmatrix.sync.aligned.m8n8.x4.shared.b16 {%0,%1,%2,%3}, [%4];"
                 : "=r"(r[0]), "=r"(r[1]), "=r"(r[2]), "=r"(r[3]) : "r"(addr));
}
__device__ __forceinline__ void mma_bf16(float* c, const uint32_t* a, const uint32_t* b) {
    asm volatile("mma.sync.aligned.m16n8k16.row.col.f32.bf16.bf16.f32 "
                 "{%0,%1,%2,%3}, {%4,%5,%6,%7}, {%8,%9}, {%0,%1,%2,%3};"
                 : "+f"(c[0]), "+f"(c[1]), "+f"(c[2]), "+f"(c[3])
                 : "r"(a[0]), "r"(a[1]), "r"(a[2]), "r"(a[3]),
                   "r"(b[0]), "r"(b[1]));
}
__device__ __forceinline__ void cvt2(float a, float b, uint32_t& h, uint32_t& l) {
    __nv_bfloat162 hb = __floats2bfloat162_rn(a, b);
    float2 hf = __bfloat1622float2(hb);
    __nv_bfloat162 lb = __floats2bfloat162_rn(a - hf.x, b - hf.y);
    h = *reinterpret_cast<uint32_t*>(&hb);
    l = *reinterpret_cast<uint32_t*>(&lb);
}

// ---------------------------------------------------------------------------
// cp.async-pipelined HMMA GEMM, 2-stage ring, 4 CTAs/SM, 1 barrier/slab.
// A (W) staged fp32 via cp.async (conflict-free 160B rows);
// B (rec) LDG->reg->block convert->bf16 smem; ldmatrix.x4 B fragments.
// bf16 3-product (hh+hl+lh), fp32 accum. warp = 16 o x 32 t.
// ---------------------------------------------------------------------------
__global__ void __launch_bounds__(256, 4)
gemm_pipe(const float* __restrict__ rec, const float* __restrict__ wgt)
{
    extern __shared__ __align__(128) char smem[];
    const uint32_t sbase = smem_u32(smem);

    const int tid = threadIdx.x;
    const int wid = tid >> 5;
    const int lid = tid & 31;
    const int g   = lid >> 2;
    const int tig = lid & 3;
    const int ot  = blockIdx.x;        // 0..3
    const int sp  = blockIdx.y;        // 0..147
    const int obase = ot * 128;

    const int s_begin = sp * SBASE + (sp < SREM ? sp : SREM);
    const int s_count = SBASE + (sp < SREM ? 1 : 0);

    // ---- A staging map: thread covers rows (tid>>3)+32j, chunk tid&7 ----
    const float* asrc0 = wgt + (size_t)(obase + (tid >> 3)) * KD
                         + (size_t)s_begin * KSLAB + (tid & 7) * 4;
    const uint32_t adst0 = sbase + (uint32_t)((tid >> 3) * A_STRIDE + (tid & 7) * 16);

#define ISSUE(S)                                                              \
    {   const uint32_t so = (uint32_t)((S) & 1) * STAGE_BYTES;                 \
        const size_t ko = (size_t)(S) * KSLAB;                                 \
        cp16(adst0 + so,                    asrc0 + ko);                       \
        cp16(adst0 + so + 32 * A_STRIDE,    asrc0 + ko + (size_t)32 * KD);     \
        cp16(adst0 + so + 64 * A_STRIDE,    asrc0 + ko + (size_t)64 * KD);     \
        cp16(adst0 + so + 96 * A_STRIDE,    asrc0 + ko + (size_t)96 * KD); }

    // ---- B map: thread covers row tid>>3, chunk tid&7 (4 floats) ----
    const int brow = tid >> 3, bchk = tid & 7;
    const float* bsrc = rec + (size_t)brow * KD
                        + (size_t)s_begin * KSLAB + bchk * 4;
    const uint32_t cvt_h = sbase + (uint32_t)(BH_OFF + brow * BB_STRIDE + bchk * 8);
    const uint32_t cvt_l = sbase + (uint32_t)(BL_OFF + brow * BB_STRIDE + bchk * 8);

    // ---- compute lane addresses ----
    const uint32_t a0b = sbase + (uint32_t)((wid * 16 + g) * A_STRIDE + tig * 8);
    const uint32_t a1b = a0b + 8 * A_STRIDE;
    // ldsm x4 B address: lanes 0-15 -> n-tile nt, lanes 16-31 -> nt+1
    const uint32_t bb  = sbase + (uint32_t)(BH_OFF + (lid & 7) * BB_STRIDE
                          + ((lid >> 3) & 1) * 16
                          + (lid >> 4) * (8 * BB_STRIDE));

    float acc[4][4];
#pragma unroll
    for (int nt = 0; nt < 4; nt++)
#pragma unroll
        for (int i = 0; i < 4; i++) acc[nt][i] = 0.0f;

    // prologue
    ISSUE(0) asm volatile("cp.async.commit_group;" ::: "memory");
    float4 breg = *reinterpret_cast<const float4*>(bsrc);

    for (int s = 0; s < s_count; s++) {
        asm volatile("cp.async.wait_group 0;" ::: "memory");

        const uint32_t so = (uint32_t)(s & 1) * STAGE_BYTES;

        // block-shared B convert from registers into bf16 hi/lo tiles
        {
            uint32_t h0, l0, h1, l1;
            cvt2(breg.x, breg.y, h0, l0);
            cvt2(breg.z, breg.w, h1, l1);
            sts64(cvt_h + so, h0, h1);
            sts64(cvt_l + so, l0, l1);
        }
        __syncthreads();   // publishes A(s) + converted B(s); frees slot s^1

        if (s + 1 < s_count) {
            ISSUE(s + 1)
            breg = *reinterpret_cast<const float4*>(bsrc + (size_t)(s + 1) * KSLAB);
        }
        asm volatile("cp.async.commit_group;" ::: "memory");

#pragma unroll
        for (int ks = 0; ks < 2; ks++) {
            const uint32_t ao = so + ks * 64;
            const float2 f0 = lds64(a0b + ao);
            const float2 f1 = lds64(a1b + ao);
            const float2 f2 = lds64(a0b + ao + 32);
            const float2 f3 = lds64(a1b + ao + 32);
            uint32_t Ah[4], Al[4];
            cvt2(f0.x, f0.y, Ah[0], Al[0]);
            cvt2(f1.x, f1.y, Ah[1], Al[1]);
            cvt2(f2.x, f2.y, Ah[2], Al[2]);
            cvt2(f3.x, f3.y, Ah[3], Al[3]);
            const uint32_t bo = bb + so + ks * 32;
#pragma unroll
            for (int np = 0; np < 2; np++) {
                uint32_t Bh[4], Bl[4];          // two n-tiles per ldsm.x4
                ldsm_x4(Bh, bo + np * (16 * BB_STRIDE));
                ldsm_x4(Bl, bo + np * (16 * BB_STRIDE) + (BL_OFF - BH_OFF));
                mma_bf16(acc[np * 2 + 0], Ah, Bh + 0);
                mma_bf16(acc[np * 2 + 0], Ah, Bl + 0);
                mma_bf16(acc[np * 2 + 0], Al, Bh + 0);
                mma_bf16(acc[np * 2 + 1], Ah, Bh + 2);
                mma_bf16(acc[np * 2 + 1], Ah, Bl + 2);
                mma_bf16(acc[np * 2 + 1], Al, Bh + 2);
            }
        }
    }

    // epilogue
    const int orow = obase + wid * 16 + g;
#pragma unroll
    for (int nt = 0; nt < 4; nt++)
#pragma unroll
        for (int c = 0; c < 4; c++) {
            const int o = orow + ((c >> 1) ? 8 : 0);
            const int t = nt * 8 + 2 * tig + (c & 1);
            g_partial[((size_t)sp * T_DIM + t) * K2 + o] = acc[nt][c];
        }
}

// ---------------------------------------------------------------------------
// deterministic split-K reduction
// ---------------------------------------------------------------------------
__global__ void __launch_bounds__(512) reduce_kernel()
{
    const int t = blockIdx.x;
    const int o = threadIdx.x;
    const size_t stride = (size_t)T_DIM * K2;
    const size_t idx = (size_t)t * K2 + o;
    float s = 0.0f;
#pragma unroll
    for (int sp = 0; sp < KSPLIT; sp++)
        s += g_partial[(size_t)sp * stride + idx];
    g_dot[t * K2 + o] = s;
}

// ---------------------------------------------------------------------------
// post: threshold -> first-spike -> totals -> 8-round k-WTA (shuffle argmax)
// ---------------------------------------------------------------------------
__global__ void __launch_bounds__(512) post_kernel(float* __restrict__ outp)
{
    const int o    = threadIdx.x;
    const int lane = o & 31;
    const int w    = o >> 5;

    unsigned mask = 0;
    int cnt = 0;
#pragma unroll
    for (int t = 0; t < T_DIM; t++) {
        const float v = g_dot[t * K2 + o];
        if (v >= THRESH) { cnt++; mask |= (1u << t); }
    }
    int first = T_DIM - cnt;
    if (first > T_DIM - 1) first = T_DIM - 1;
    const float fv    = g_dot[first * K2 + o];
    const float value = (fv < THRESH) ? 0.0f : fv;
    const float cand  = (cnt > 0) ? value : 0.0f;

    __shared__ float wmaxf[16];
    __shared__ unsigned long long wmax[16];
    __shared__ int s_win;

    float m = cand;
#pragma unroll
    for (int off = 16; off; off >>= 1)
        m = fmaxf(m, __shfl_xor_sync(0xffffffffu, m, off));
    if (lane == 0) wmaxf[w] = m;
    __syncthreads();
    if (o == 0) {
        float mm = wmaxf[0];
#pragma unroll
        for (int i = 1; i < 16; i++) mm = fmaxf(mm, wmaxf[i]);
        wmaxf[0] = mm;
    }
    __syncthreads();
    const float voff = wmaxf[0] * (float)T_DIM;

    float tot = (cnt > 0) ? (float)cnt * (value + voff) : 0.0f;
    bool sel = false;

    for (int r = 0; r < 8; r++) {
        unsigned long long pk =
            ((unsigned long long)__float_as_uint(tot) << 32)
            | (unsigned)(K2 - 1 - o);
#pragma unroll
        for (int off = 16; off; off >>= 1) {
            unsigned long long other = __shfl_xor_sync(0xffffffffu, pk, off);
            if (other > pk) pk = other;
        }
        if (lane == 0) wmax[w] = pk;
        __syncthreads();
        if (o == 0) {
            unsigned long long best = wmax[0];
#pragma unroll
            for (int i = 1; i < 16; i++) if (wmax[i] > best) best = wmax[i];
            s_win = (K2 - 1) - (int)(unsigned)(best & 0xffffffffULL);
        }
        __syncthreads();
        if (o == s_win) {
            if (tot != 0.0f) sel = true;
            tot = 0.0f;
        }
        __syncthreads();
    }

#pragma unroll
    for (int t = 0; t < T_DIM; t++) {
        outp[t * K2 + o] = (sel && ((mask >> t) & 1u)) ? 1.0f : 0.0f;
    }
}

// ---------------------------------------------------------------------------
extern "C" void kernel_launch(void* const* d_in, const int* in_sizes, int n_in,
                              void* d_out, int out_size)
{
    const float* rec = (const float*)d_in[0];   // (32,1,64,4096)
    const float* wgt = (const float*)d_in[1];   // (512,1,64,4096)
    if (n_in >= 2 && in_sizes[0] > in_sizes[1]) {
        const float* tmp = rec; rec = wgt; wgt = tmp;
    }
    float* outp = (float*)d_out;

    cudaFuncSetAttribute(gemm_pipe, cudaFuncAttributeMaxDynamicSharedMemorySize,
                         SMEM_TOTAL);

    gemm_pipe<<<dim3(4, KSPLIT), 256, SMEM_TOTAL>>>(rec, wgt);
    reduce_kernel<<<T_DIM, K2>>>();
    post_kernel<<<1, K2>>>(outp);
}